// round 14
// baseline (speedup 1.0000x reference)
#include <cuda_runtime.h>
#include <cuda_bf16.h>
#include <cuda_fp16.h>
#include <math.h>
#include <stdint.h>

#define NB 8
#define NC 512
#define NL 1024
#define NH 8
#define DH 64
#define WIN 4
#define NT 9   // 2*WIN+1

// Scratch (allocation-free contract).
__device__ __half g_q [NB * NC * NL];     // q fp16 [b][c][l] (scale folded)
__device__ __half g_k [NB * NC * NL];     // k fp16
__device__ __half g_v [NB * NC * NL];     // v fp16
__device__ __half g_xT[NB * NL * NC];     // x transposed [b][l][c], fp16
__device__ __half g_tT[NB * NL * NC];     // attn out transposed [b][l][c], fp16
__device__ __half g_Wh[4 * NC * NC];      // Wq*0.125, Wk, Wv, Wo : fp16 hi
__device__ __half g_Wl[4 * NC * NC];      // fp16 lo (used for Wo only)

// ---------------- PTX helpers (sm_80-portable only) ----------------
__device__ __forceinline__ void cp16(uint32_t dst, const void* src) {
    asm volatile("cp.async.cg.shared.global [%0], [%1], 16;" :: "r"(dst), "l"(src));
}
__device__ __forceinline__ void cp_commit() { asm volatile("cp.async.commit_group;"); }
__device__ __forceinline__ void cp_wait0() { asm volatile("cp.async.wait_group 0;" ::: "memory"); }
__device__ __forceinline__ void cp_wait1() { asm volatile("cp.async.wait_group 1;" ::: "memory"); }

__device__ __forceinline__ uint32_t smem_u32(const void* p) {
    uint32_t a;
    asm("{ .reg .u64 t; cvta.to.shared.u64 t, %1; cvt.u32.u64 %0, t; }" : "=r"(a) : "l"(p));
    return a;
}
__device__ __forceinline__ void ld4(uint32_t* r, uint32_t addr) {
    asm volatile("ldmatrix.sync.aligned.m8n8.x4.shared.b16 {%0,%1,%2,%3}, [%4];"
                 : "=r"(r[0]), "=r"(r[1]), "=r"(r[2]), "=r"(r[3]) : "r"(addr));
}
__device__ __forceinline__ void ld4t(uint32_t* r, uint32_t addr) {
    asm volatile("ldmatrix.sync.aligned.m8n8.x4.trans.shared.b16 {%0,%1,%2,%3}, [%4];"
                 : "=r"(r[0]), "=r"(r[1]), "=r"(r[2]), "=r"(r[3]) : "r"(addr));
}
// volatile: measured fastest (R5/R9/R10/R11).
__device__ __forceinline__ void mma_f16(float* d, const uint32_t* a, const uint32_t* b) {
    asm volatile(
        "mma.sync.aligned.m16n8k16.row.col.f32.f16.f16.f32 "
        "{%0,%1,%2,%3}, {%4,%5,%6,%7}, {%8,%9}, {%0,%1,%2,%3};"
        : "+f"(d[0]), "+f"(d[1]), "+f"(d[2]), "+f"(d[3])
        : "r"(a[0]), "r"(a[1]), "r"(a[2]), "r"(a[3]), "r"(b[0]), "r"(b[1]));
}
__device__ __forceinline__ uint32_t pack2h(float v0, float v1) {
    __half2 p = __halves2half2(__float2half(v0), __float2half(v1));
    return *(uint32_t*)&p;
}

// ---------------------------------------------------------------------------
// Prep kernels (R12-exact).
// ---------------------------------------------------------------------------
__global__ void split_w(const float* __restrict__ w0, const float* __restrict__ w1,
                        const float* __restrict__ w2, const float* __restrict__ w3)
{
    int widx = blockIdx.y;
    const float* w = widx == 0 ? w0 : widx == 1 ? w1 : widx == 2 ? w2 : w3;
    float alpha = (widx == 0) ? 0.125f : 1.f;
    int e = blockIdx.x * 256 + threadIdx.x;
    float v = w[e] * alpha;
    __half hi = __float2half(v);
    g_Wh[widx * NC * NC + e] = hi;
    g_Wl[widx * NC * NC + e] = __float2half(v - __half2float(hi));
}

__global__ __launch_bounds__(256) void split_xT(const float* __restrict__ x)
{
    __shared__ float tile[32][33];
    int b = blockIdx.z, c0 = blockIdx.y * 32, l0 = blockIdx.x * 32;
    const float* xb = x + ((size_t)b * NC + c0) * NL + l0;
    int tx = threadIdx.x & 31, ty = threadIdx.x >> 5;
#pragma unroll
    for (int i = 0; i < 4; i++)
        tile[ty + i * 8][tx] = xb[(size_t)(ty + i * 8) * NL + tx];
    __syncthreads();
    size_t ob = ((size_t)b * NL + l0) * NC + c0;
#pragma unroll
    for (int i = 0; i < 4; i++) {
        int r = ty + i * 8;
        g_xT[ob + (size_t)r * NC + tx] = __float2half(tile[tx][r]);
    }
}

// ---------------------------------------------------------------------------
// mma.sync fp16 GEMM (R12-exact).
// ---------------------------------------------------------------------------
#define KC 32
#define RS 40
#define MAT_B (128 * RS * 2)     // 10240

template<bool QKV>
__global__ __launch_bounds__(256) void gemm_mma(
    const __half* __restrict__ Whi, const __half* __restrict__ Wlo,
    const __half* __restrict__ Bx,
    const float* __restrict__ b0, const float* __restrict__ b1,
    const float* __restrict__ b2, float* __restrict__ Y)
{
    extern __shared__ __align__(128) char smem[];
    const int NMAT = QKV ? 2 : 3;
    const int BUFB = NMAT * MAT_B;
    const int XOFF = (NMAT - 1) * MAT_B;

    const int b  = blockIdx.z;
    int which = 0, m0;
    if (QKV) { which = blockIdx.y >> 2; m0 = (blockIdx.y & 3) * 128; }
    else     { m0 = blockIdx.y * 128; }
    const int n0 = blockIdx.x * 128;

    const __half* Ahi = Whi + (size_t)which * NC * NC;
    const __half* Alo = Wlo + (size_t)which * NC * NC;
    const float* bias = QKV ? (which == 0 ? b0 : which == 1 ? b1 : b2) : b0;
    const __half* Bx_b = Bx + (size_t)b * NL * NC;

    const int t = threadIdx.x;
    const int warp = t >> 5, lane = t & 31;
    const int wm = (warp >> 2) * 64;
    const int wn = (warp & 3) * 32;
    const uint32_t sbase = smem_u32(smem);

    const int a_lr = lane & 15;
    const int a_hc = (lane >> 4) * 8;
    const int b_nr = (lane & 7) + ((lane >> 4) << 3);
    const int b_kc = ((lane >> 3) & 1) * 8;

    auto load_chunk = [&](int buf, int k0) {
        const int ITERS = QKV ? 4 : 6;
#pragma unroll
        for (int it = 0; it < ITERS; it++) {
            int u = t + it * 256;
            int mat = u >> 9, rem = u & 511;
            int row = rem >> 2, c16 = rem & 3;
            const __half* src;
            if (mat == 0)                src = Ahi  + (size_t)(m0 + row) * NC + k0 + c16 * 8;
            else if (!QKV && mat == 1)   src = Alo  + (size_t)(m0 + row) * NC + k0 + c16 * 8;
            else                         src = Bx_b + (size_t)(n0 + row) * NC + k0 + c16 * 8;
            cp16(sbase + buf * BUFB + mat * MAT_B + row * (RS * 2) + c16 * 16, src);
        }
        cp_commit();
    };

    float d[4][4][4];
#pragma unroll
    for (int mi = 0; mi < 4; mi++)
#pragma unroll
        for (int ni = 0; ni < 4; ni++)
#pragma unroll
            for (int q = 0; q < 4; q++) d[mi][ni][q] = 0.f;

    load_chunk(0, 0);

    for (int ch = 0; ch < NC / KC; ch++) {
        const int buf = ch & 1;
        if (ch + 1 < NC / KC) { load_chunk(buf ^ 1, (ch + 1) * KC); cp_wait1(); }
        else cp_wait0();
        __syncthreads();

        const uint32_t base = sbase + buf * BUFB;
#pragma unroll
        for (int ks = 0; ks < 2; ks++) {
            const int kc = ks * 16;
            uint32_t ah[4][4], al[4][4], bb[4][2];
#pragma unroll
            for (int mi = 0; mi < 4; mi++) {
                uint32_t r = (wm + mi * 16 + a_lr) * (RS * 2) + (kc + a_hc) * 2;
                ld4(ah[mi], base + r);
                if (!QKV) ld4(al[mi], base + MAT_B + r);
            }
#pragma unroll
            for (int pi = 0; pi < 2; pi++) {
                uint32_t r = (wn + pi * 16 + b_nr) * (RS * 2) + (kc + b_kc) * 2;
                uint32_t tmp[4];
                ld4(tmp, base + XOFF + r);
                bb[2 * pi][0] = tmp[0]; bb[2 * pi][1] = tmp[1];
                bb[2 * pi + 1][0] = tmp[2]; bb[2 * pi + 1][1] = tmp[3];
            }
#pragma unroll
            for (int mi = 0; mi < 4; mi++)
#pragma unroll
                for (int ni = 0; ni < 4; ni++) {
                    mma_f16(d[mi][ni], ah[mi], bb[ni]);
                    if (!QKV) mma_f16(d[mi][ni], al[mi], bb[ni]);
                }
        }
        __syncthreads();
    }

    const int erow = lane >> 2, ecol = 2 * (lane & 3);
#pragma unroll
    for (int mi = 0; mi < 4; mi++) {
        int mA = m0 + wm + mi * 16 + erow;
        float bvA = __ldg(bias + mA);
        float bvB = __ldg(bias + mA + 8);
        if (!QKV) {
            float* rowA = Y + (size_t)b * NC * NL + (size_t)mA * NL + n0 + wn + ecol;
            float* rowB = rowA + 8 * NL;
#pragma unroll
            for (int ni = 0; ni < 4; ni++) {
                *(float2*)(rowA + ni * 8) = make_float2(d[mi][ni][0] + bvA, d[mi][ni][1] + bvA);
                *(float2*)(rowB + ni * 8) = make_float2(d[mi][ni][2] + bvB, d[mi][ni][3] + bvB);
            }
        } else {
            __half* Yq = (which == 0 ? g_q : which == 1 ? g_k : g_v);
            float s = (which == 0) ? 0.125f : 1.f;
            __half* ohA = Yq + ((size_t)b * NC + mA) * NL + n0 + wn + ecol;
            __half* ohB = ohA + 8 * NL;
#pragma unroll
            for (int ni = 0; ni < 4; ni++) {
                *(uint32_t*)(ohA + ni * 8) = pack2h(d[mi][ni][0] + bvA * s, d[mi][ni][1] + bvA * s);
                *(uint32_t*)(ohB + ni * 8) = pack2h(d[mi][ni][2] + bvB * s, d[mi][ni][3] + bvB * s);
            }
        }
    }
}

// ---------------------------------------------------------------------------
// Tensor-core flash attention, no-max softmax, single fp16, 128-row Q tile.
// Each warp owns 32 Q rows (two m16 groups) -> each K/V ldmatrix feeds 4 MMAs.
// Smem: Q (64 d x 128 l, pitch 136) + double-buffered [K, V] + f32 tables.
// ---------------------------------------------------------------------------
#define P72 72
#define PQ 136
#define QTILB (64 * PQ * 2)      // 17408
#define TILB (64 * P72 * 2)      // 9216
#define OQ 0
#define OKV QTILB                // buffer b at OKV + b*2*TILB: [K, V]
#define OF32 (OKV + 4 * TILB)    // 54272
#define ATTN_SMEM (OF32 + (1152 + 1152 + 576) * 4)   // 65792

__global__ __launch_bounds__(128, 2) void attn_tc(
    const float* __restrict__ erk, const float* __restrict__ erv)
{
    extern __shared__ __align__(128) char sm[];
    const uint32_t sb = smem_u32(sm);
    float* rqs  = (float*)(sm + OF32);       // 128 x NT
    float* arel = rqs + 1152;                // 128 x NT
    float* ervs = arel + 1152;               // NT x DH

    const int bh = blockIdx.y, b = bh >> 3, h = bh & 7;
    const int i0 = blockIdx.x * 128;
    const size_t gb = ((size_t)b * NC + h * DH) * NL;
    const __half* gq = g_q + gb;
    const __half* gkv[2] = {g_k + gb, g_v + gb};

    const int t = threadIdx.x, lane = t & 31, w = t >> 5;
    const int lr = lane >> 2, lc = 2 * (lane & 3);

    const int qrow = (lane & 7) + ((lane >> 4) & 1) * 8, qcol = ((lane >> 3) & 1) * 8;
    const int krow = (lane & 7) + ((lane >> 3) & 1) * 8, kcol = ((lane >> 4) & 1) * 8;
    const int vrow = (lane & 7) + ((lane >> 4) & 1) * 8, vcol = ((lane >> 3) & 1) * 8;

    // Q tile: 64 d-rows x 128 l-cols = 1024 x 16B chunks
#pragma unroll
    for (int it = 0; it < 8; it++) {
        int e = t + it * 128;
        int row = e >> 4, c16 = e & 15;
        cp16(sb + OQ + row * (PQ * 2) + c16 * 16,
             gq + (size_t)row * NL + i0 + c16 * 8);
    }
    cp_commit();

    auto issue_kv = [&](int buf, int j0g) {
#pragma unroll
        for (int it = 0; it < 8; it++) {
            int e = t + it * 128;
            int mat = e >> 9, rem = e & 511, row = rem >> 3, c16 = rem & 7;
            cp16(sb + OKV + buf * 2 * TILB + mat * TILB + row * (P72 * 2) + c16 * 16,
                 gkv[mat] + (size_t)row * NL + j0g + c16 * 8);
        }
        cp_commit();
    };
    issue_kv(0, 0);

    for (int e = t; e < NT * DH; e += 128) ervs[e] = erv[e];

    cp_wait1();
    __syncthreads();

    // rq[r][tt] = sum_d q[d][r] * erk[tt][d]; arel = 0  (128 rows)
    {
        const __half* qs = (const __half*)(sm + OQ);
        for (int e = t; e < 128 * NT; e += 128) {
            int r = e / NT, tt = e % NT;
            float s = 0.f;
#pragma unroll 16
            for (int d = 0; d < DH; d++)
                s = fmaf(__half2float(qs[d * PQ + r]), erk[tt * DH + d], s);
            rqs[e] = s;
            arel[e] = 0.f;
        }
    }

    // Q fragments: 2 row-groups (g) x 4 k-chunks
    uint32_t qf[4][2][4];
#pragma unroll
    for (int kc = 0; kc < 4; kc++)
#pragma unroll
        for (int g = 0; g < 2; g++) {
            uint32_t r = ((kc * 16 + qrow) * PQ + 32 * w + 16 * g + qcol) * 2;
            ld4t(qf[kc][g], sb + OQ + r);
        }
    __syncthreads();

    float l[4] = {0.f, 0.f, 0.f, 0.f};
    float o[2][8][4];
#pragma unroll
    for (int g = 0; g < 2; g++)
#pragma unroll
        for (int sbk = 0; sbk < 8; sbk++)
#pragma unroll
            for (int q = 0; q < 4; q++) o[g][sbk][q] = 0.f;

    const int r0 = 32 * w + lr;   // thread rows: r0 + 8u, u in 0..3

    for (int jt = 0; jt < 16; jt++) {
        const int j0 = jt * 64;
        const int buf = jt & 1;
        const bool band = (j0 >= i0 - 64) && (j0 <= i0 + 128);

        __syncthreads();
        if (jt + 1 < 16) { issue_kv(buf ^ 1, j0 + 64); cp_wait1(); }
        else cp_wait0();
        __syncthreads();

        // ---- S = Q K^T : each ld4t feeds 4 MMAs ----
        float s[2][8][4];
#pragma unroll
        for (int g = 0; g < 2; g++)
#pragma unroll
            for (int sbk = 0; sbk < 8; sbk++)
#pragma unroll
                for (int q = 0; q < 4; q++) s[g][sbk][q] = 0.f;

        const uint32_t k_b = sb + OKV + buf * 2 * TILB;
#pragma unroll
        for (int nb = 0; nb < 4; nb++) {
#pragma unroll
            for (int kc = 0; kc < 4; kc++) {
                uint32_t r = ((kc * 16 + krow) * P72 + nb * 16 + kcol) * 2;
                uint32_t k4[4];
                ld4t(k4, k_b + r);
#pragma unroll
                for (int g = 0; g < 2; g++) {
                    mma_f16(s[g][2 * nb],     qf[kc][g], k4);
                    mma_f16(s[g][2 * nb + 1], qf[kc][g], k4 + 2);
                }
            }
        }

        // ---- rel_k band add ----
        if (band) {
#pragma unroll
            for (int g = 0; g < 2; g++) {
                int row0 = r0 + 16 * g, row1 = row0 + 8;
#pragma unroll
                for (int sbk = 0; sbk < 8; sbk++) {
                    int jg = j0 + sbk * 8 + lc;
                    int t00 = jg - (i0 + row0) + WIN;
                    int t10 = jg - (i0 + row1) + WIN;
                    if (t00 >= 0 && t00 < NT)     s[g][sbk][0] += rqs[row0 * NT + t00];
                    if (t00 + 1 >= 0 && t00 + 1 < NT) s[g][sbk][1] += rqs[row0 * NT + t00 + 1];
                    if (t10 >= 0 && t10 < NT)     s[g][sbk][2] += rqs[row1 * NT + t10];
                    if (t10 + 1 >= 0 && t10 + 1 < NT) s[g][sbk][3] += rqs[row1 * NT + t10 + 1];
                }
            }
        }

        // ---- exp + accumulate (no max subtraction; headroom proven) ----
#pragma unroll
        for (int g = 0; g < 2; g++)
#pragma unroll
            for (int sbk = 0; sbk < 8; sbk++) {
                s[g][sbk][0] = __expf(s[g][sbk][0]); l[2 * g]     += s[g][sbk][0];
                s[g][sbk][1] = __expf(s[g][sbk][1]); l[2 * g]     += s[g][sbk][1];
                s[g][sbk][2] = __expf(s[g][sbk][2]); l[2 * g + 1] += s[g][sbk][2];
                s[g][sbk][3] = __expf(s[g][sbk][3]); l[2 * g + 1] += s[g][sbk][3];
            }

        // ---- band probability accumulator ----
        if (band) {
#pragma unroll
            for (int g = 0; g < 2; g++) {
                int row0 = r0 + 16 * g, row1 = row0 + 8;
#pragma unroll
                for (int sbk = 0; sbk < 8; sbk++) {
                    int jg = j0 + sbk * 8 + lc;
                    int t00 = jg - (i0 + row0) + WIN;
                    int t10 = jg - (i0 + row1) + WIN;
                    if (t00 >= 0 && t00 < NT)     arel[row0 * NT + t00]     += s[g][sbk][0];
                    if (t00 + 1 >= 0 && t00 + 1 < NT) arel[row0 * NT + t00 + 1] += s[g][sbk][1];
                    if (t10 >= 0 && t10 < NT)     arel[row1 * NT + t10]     += s[g][sbk][2];
                    if (t10 + 1 >= 0 && t10 + 1 < NT) arel[row1 * NT + t10 + 1] += s[g][sbk][3];
                }
            }
        }

        // ---- pack P ----
        uint32_t pa[2][4][4];
#pragma unroll
        for (int g = 0; g < 2; g++)
#pragma unroll
            for (int kc = 0; kc < 4; kc++) {
                pa[g][kc][0] = pack2h(s[g][2 * kc][0],     s[g][2 * kc][1]);
                pa[g][kc][1] = pack2h(s[g][2 * kc][2],     s[g][2 * kc][3]);
                pa[g][kc][2] = pack2h(s[g][2 * kc + 1][0], s[g][2 * kc + 1][1]);
                pa[g][kc][3] = pack2h(s[g][2 * kc + 1][2], s[g][2 * kc + 1][3]);
            }

        // ---- O += P V : each ld4 feeds 4 MMAs ----
        const uint32_t v_b = k_b + TILB;
#pragma unroll
        for (int nb = 0; nb < 4; nb++) {
#pragma unroll
            for (int kc = 0; kc < 4; kc++) {
                uint32_t r = ((nb * 16 + vrow) * P72 + kc * 16 + vcol) * 2;
                uint32_t v4[4];
                ld4(v4, v_b + r);
#pragma unroll
                for (int g = 0; g < 2; g++) {
                    mma_f16(o[g][2 * nb],     pa[g][kc], v4);
                    mma_f16(o[g][2 * nb + 1], pa[g][kc], v4 + 2);
                }
            }
        }
    }

    // ---- final row-sum reduce ----
#pragma unroll
    for (int u = 0; u < 4; u++) {
        l[u] += __shfl_xor_sync(0xffffffffu, l[u], 1);
        l[u] += __shfl_xor_sync(0xffffffffu, l[u], 2);
    }
    __syncwarp();

    float inv[4];
#pragma unroll
    for (int u = 0; u < 4; u++) inv[u] = 1.f / l[u];
    float ar[4][NT];
#pragma unroll
    for (int u = 0; u < 4; u++)
#pragma unroll
        for (int tt = 0; tt < NT; tt++)
            ar[u][tt] = arel[(r0 + 8 * u) * NT + tt];

    __half* tp[4];
#pragma unroll
    for (int u = 0; u < 4; u++)
        tp[u] = g_tT + ((size_t)b * NL + i0 + r0 + 8 * u) * NC + h * DH;

#pragma unroll
    for (int sbk = 0; sbk < 8; sbk++) {
        int d0 = sbk * 8 + lc;
        float rr[4][2];
#pragma unroll
        for (int u = 0; u < 4; u++) { rr[u][0] = 0.f; rr[u][1] = 0.f; }
#pragma unroll
        for (int tt = 0; tt < NT; tt++) {
            float e0 = ervs[tt * DH + d0], e1 = ervs[tt * DH + d0 + 1];
#pragma unroll
            for (int u = 0; u < 4; u++) {
                rr[u][0] = fmaf(ar[u][tt], e0, rr[u][0]);
                rr[u][1] = fmaf(ar[u][tt], e1, rr[u][1]);
            }
        }
        *(uint32_t*)(tp[0] + d0) = pack2h((o[0][sbk][0] + rr[0][0]) * inv[0],
                                          (o[0][sbk][1] + rr[0][1]) * inv[0]);
        *(uint32_t*)(tp[1] + d0) = pack2h((o[0][sbk][2] + rr[1][0]) * inv[1],
                                          (o[0][sbk][3] + rr[1][1]) * inv[1]);
        *(uint32_t*)(tp[2] + d0) = pack2h((o[1][sbk][0] + rr[2][0]) * inv[2],
                                          (o[1][sbk][1] + rr[2][1]) * inv[2]);
        *(uint32_t*)(tp[3] + d0) = pack2h((o[1][sbk][2] + rr[3][0]) * inv[3],
                                          (o[1][sbk][3] + rr[3][1]) * inv[3]);
    }
}

// ---------------------------------------------------------------------------
extern "C" void kernel_launch(void* const* d_in, const int* in_sizes, int n_in,
                              void* d_out, int out_size)
{
    const float* x   = (const float*)d_in[0];
    const float* Wq  = (const float*)d_in[1];
    const float* bq  = (const float*)d_in[2];
    const float* Wk  = (const float*)d_in[3];
    const float* bk  = (const float*)d_in[4];
    const float* Wv  = (const float*)d_in[5];
    const float* bv  = (const float*)d_in[6];
    const float* Wo  = (const float*)d_in[7];
    const float* bo  = (const float*)d_in[8];
    const float* erk = (const float*)d_in[9];
    const float* erv = (const float*)d_in[10];
    float* out = (float*)d_out;

    __half *xT, *tT, *wh, *wl;
    cudaGetSymbolAddress((void**)&xT, g_xT);
    cudaGetSymbolAddress((void**)&tT, g_tT);
    cudaGetSymbolAddress((void**)&wh, g_Wh);
    cudaGetSymbolAddress((void**)&wl, g_Wl);

    const int qkv_smem = 2 * 2 * MAT_B;   // 40960
    const int wo_smem  = 2 * 3 * MAT_B;   // 61440
    cudaFuncSetAttribute(gemm_mma<true>,
                         cudaFuncAttributeMaxDynamicSharedMemorySize, qkv_smem);
    cudaFuncSetAttribute(gemm_mma<false>,
                         cudaFuncAttributeMaxDynamicSharedMemorySize, wo_smem);
    cudaFuncSetAttribute(attn_tc,
                         cudaFuncAttributeMaxDynamicSharedMemorySize, ATTN_SMEM);

    split_w<<<dim3(NC * NC / 256, 4), 256>>>(Wq, Wk, Wv, Wo);
    split_xT<<<dim3(NL / 32, NC / 32, NB), 256>>>(x);

    const int WSZ = NC * NC;
    gemm_mma<true><<<dim3(NL / 128, 12, NB), 256, qkv_smem>>>(
        wh, wl, xT, bq, bk, bv, nullptr);

    dim3 ga(NL / 128, NB * NH);   // (8, 64)
    attn_tc<<<ga, 128, ATTN_SMEM>>>(erk, erv);

    gemm_mma<false><<<dim3(NL / 128, 4, NB), 256, wo_smem>>>(
        wh + 3 * WSZ, wl + 3 * WSZ, tT, bo, nullptr, nullptr, out);
}

// round 15
// speedup vs baseline: 1.0935x; 1.0935x over previous
#include <cuda_runtime.h>
#include <cuda_bf16.h>
#include <cuda_fp16.h>
#include <math.h>
#include <stdint.h>

#define NB 8
#define NC 512
#define NL 1024
#define NH 8
#define DH 64
#define WIN 4
#define NT 9   // 2*WIN+1

// Scratch (allocation-free contract).
__device__ __half g_q [NB * NC * NL];     // q fp16 [b][c][l] (scale folded)
__device__ __half g_k [NB * NC * NL];     // k fp16
__device__ __half g_v [NB * NC * NL];     // v fp16
__device__ __half g_xT[NB * NL * NC];     // x transposed [b][l][c], fp16
__device__ __half g_tT[NB * NL * NC];     // attn out transposed [b][l][c], fp16
__device__ __half g_Wh[4 * NC * NC];      // Wq*0.125, Wk, Wv, Wo : fp16

// ---------------- PTX helpers (sm_80-portable only) ----------------
__device__ __forceinline__ void cp16(uint32_t dst, const void* src) {
    asm volatile("cp.async.cg.shared.global [%0], [%1], 16;" :: "r"(dst), "l"(src));
}
__device__ __forceinline__ void cp_commit() { asm volatile("cp.async.commit_group;"); }
__device__ __forceinline__ void cp_wait0() { asm volatile("cp.async.wait_group 0;" ::: "memory"); }
__device__ __forceinline__ void cp_wait1() { asm volatile("cp.async.wait_group 1;" ::: "memory"); }

__device__ __forceinline__ uint32_t smem_u32(const void* p) {
    uint32_t a;
    asm("{ .reg .u64 t; cvta.to.shared.u64 t, %1; cvt.u32.u64 %0, t; }" : "=r"(a) : "l"(p));
    return a;
}
__device__ __forceinline__ void ld4(uint32_t* r, uint32_t addr) {
    asm volatile("ldmatrix.sync.aligned.m8n8.x4.shared.b16 {%0,%1,%2,%3}, [%4];"
                 : "=r"(r[0]), "=r"(r[1]), "=r"(r[2]), "=r"(r[3]) : "r"(addr));
}
__device__ __forceinline__ void ld4t(uint32_t* r, uint32_t addr) {
    asm volatile("ldmatrix.sync.aligned.m8n8.x4.trans.shared.b16 {%0,%1,%2,%3}, [%4];"
                 : "=r"(r[0]), "=r"(r[1]), "=r"(r[2]), "=r"(r[3]) : "r"(addr));
}
// volatile: measured fastest (R5/R9/R10/R11).
__device__ __forceinline__ void mma_f16(float* d, const uint32_t* a, const uint32_t* b) {
    asm volatile(
        "mma.sync.aligned.m16n8k16.row.col.f32.f16.f16.f32 "
        "{%0,%1,%2,%3}, {%4,%5,%6,%7}, {%8,%9}, {%0,%1,%2,%3};"
        : "+f"(d[0]), "+f"(d[1]), "+f"(d[2]), "+f"(d[3])
        : "r"(a[0]), "r"(a[1]), "r"(a[2]), "r"(a[3]), "r"(b[0]), "r"(b[1]));
}
__device__ __forceinline__ uint32_t pack2h(float v0, float v1) {
    __half2 p = __halves2half2(__float2half(v0), __float2half(v1));
    return *(uint32_t*)&p;
}

// ---------------------------------------------------------------------------
// Prep kernels.
// ---------------------------------------------------------------------------
__global__ void split_w(const float* __restrict__ w0, const float* __restrict__ w1,
                        const float* __restrict__ w2, const float* __restrict__ w3)
{
    int widx = blockIdx.y;
    const float* w = widx == 0 ? w0 : widx == 1 ? w1 : widx == 2 ? w2 : w3;
    float alpha = (widx == 0) ? 0.125f : 1.f;
    int e = blockIdx.x * 256 + threadIdx.x;
    g_Wh[widx * NC * NC + e] = __float2half(w[e] * alpha);
}

__global__ __launch_bounds__(256) void split_xT(const float* __restrict__ x)
{
    __shared__ float tile[32][33];
    int b = blockIdx.z, c0 = blockIdx.y * 32, l0 = blockIdx.x * 32;
    const float* xb = x + ((size_t)b * NC + c0) * NL + l0;
    int tx = threadIdx.x & 31, ty = threadIdx.x >> 5;
#pragma unroll
    for (int i = 0; i < 4; i++)
        tile[ty + i * 8][tx] = xb[(size_t)(ty + i * 8) * NL + tx];
    __syncthreads();
    size_t ob = ((size_t)b * NL + l0) * NC + c0;
#pragma unroll
    for (int i = 0; i < 4; i++) {
        int r = ty + i * 8;
        g_xT[ob + (size_t)r * NC + tx] = __float2half(tile[tx][r]);
    }
}

// ---------------------------------------------------------------------------
// mma.sync single-term fp16 GEMM. QKV=true: fused 3-matrix launch, fp16 out.
// QKV=false: Wo, fp32 out.
// ---------------------------------------------------------------------------
#define KC 32
#define RS 40
#define MAT_B (128 * RS * 2)     // 10240
#define BUF2 (2 * MAT_B)         // 20480 (W | x)

template<bool QKV>
__global__ __launch_bounds__(256) void gemm_mma(
    const __half* __restrict__ Whi, const __half* __restrict__ Bx,
    const float* __restrict__ b0, const float* __restrict__ b1,
    const float* __restrict__ b2, float* __restrict__ Y)
{
    extern __shared__ __align__(128) char smem[];

    const int b  = blockIdx.z;
    int which = 0, m0;
    if (QKV) { which = blockIdx.y >> 2; m0 = (blockIdx.y & 3) * 128; }
    else     { m0 = blockIdx.y * 128; }
    const int n0 = blockIdx.x * 128;

    const __half* Ahi = Whi + (size_t)which * NC * NC;
    const float* bias = QKV ? (which == 0 ? b0 : which == 1 ? b1 : b2) : b0;
    const __half* Bx_b = Bx + (size_t)b * NL * NC;

    const int t = threadIdx.x;
    const int warp = t >> 5, lane = t & 31;
    const int wm = (warp >> 2) * 64;
    const int wn = (warp & 3) * 32;
    const uint32_t sbase = smem_u32(smem);

    const int a_lr = lane & 15;
    const int a_hc = (lane >> 4) * 8;
    const int b_nr = (lane & 7) + ((lane >> 4) << 3);
    const int b_kc = ((lane >> 3) & 1) * 8;

    auto load_chunk = [&](int buf, int k0) {
#pragma unroll
        for (int it = 0; it < 4; it++) {
            int u = t + it * 256;
            int mat = u >> 9, rem = u & 511;
            int row = rem >> 2, c16 = rem & 3;
            const __half* src = mat == 0
                ? Ahi  + (size_t)(m0 + row) * NC + k0 + c16 * 8
                : Bx_b + (size_t)(n0 + row) * NC + k0 + c16 * 8;
            cp16(sbase + buf * BUF2 + mat * MAT_B + row * (RS * 2) + c16 * 16, src);
        }
        cp_commit();
    };

    float d[4][4][4];
#pragma unroll
    for (int mi = 0; mi < 4; mi++)
#pragma unroll
        for (int ni = 0; ni < 4; ni++)
#pragma unroll
            for (int q = 0; q < 4; q++) d[mi][ni][q] = 0.f;

    load_chunk(0, 0);

    for (int ch = 0; ch < NC / KC; ch++) {
        const int buf = ch & 1;
        if (ch + 1 < NC / KC) { load_chunk(buf ^ 1, (ch + 1) * KC); cp_wait1(); }
        else cp_wait0();
        __syncthreads();

        const uint32_t base = sbase + buf * BUF2;
#pragma unroll
        for (int ks = 0; ks < 2; ks++) {
            const int kc = ks * 16;
            uint32_t ah[4][4], bb[4][2];
#pragma unroll
            for (int mi = 0; mi < 4; mi++) {
                uint32_t r = (wm + mi * 16 + a_lr) * (RS * 2) + (kc + a_hc) * 2;
                ld4(ah[mi], base + r);
            }
#pragma unroll
            for (int pi = 0; pi < 2; pi++) {
                uint32_t r = (wn + pi * 16 + b_nr) * (RS * 2) + (kc + b_kc) * 2;
                uint32_t tmp[4];
                ld4(tmp, base + MAT_B + r);
                bb[2 * pi][0] = tmp[0]; bb[2 * pi][1] = tmp[1];
                bb[2 * pi + 1][0] = tmp[2]; bb[2 * pi + 1][1] = tmp[3];
            }
#pragma unroll
            for (int mi = 0; mi < 4; mi++)
#pragma unroll
                for (int ni = 0; ni < 4; ni++)
                    mma_f16(d[mi][ni], ah[mi], bb[ni]);
        }
        __syncthreads();
    }

    const int erow = lane >> 2, ecol = 2 * (lane & 3);
#pragma unroll
    for (int mi = 0; mi < 4; mi++) {
        int mA = m0 + wm + mi * 16 + erow;
        float bvA = __ldg(bias + mA);
        float bvB = __ldg(bias + mA + 8);
        if (!QKV) {
            float* rowA = Y + (size_t)b * NC * NL + (size_t)mA * NL + n0 + wn + ecol;
            float* rowB = rowA + 8 * NL;
#pragma unroll
            for (int ni = 0; ni < 4; ni++) {
                *(float2*)(rowA + ni * 8) = make_float2(d[mi][ni][0] + bvA, d[mi][ni][1] + bvA);
                *(float2*)(rowB + ni * 8) = make_float2(d[mi][ni][2] + bvB, d[mi][ni][3] + bvB);
            }
        } else {
            __half* Yq = (which == 0 ? g_q : which == 1 ? g_k : g_v);
            float s = (which == 0) ? 0.125f : 1.f;   // bias scale (W pre-scaled)
            __half* ohA = Yq + ((size_t)b * NC + mA) * NL + n0 + wn + ecol;
            __half* ohB = ohA + 8 * NL;
#pragma unroll
            for (int ni = 0; ni < 4; ni++) {
                *(uint32_t*)(ohA + ni * 8) = pack2h(d[mi][ni][0] + bvA * s, d[mi][ni][1] + bvA * s);
                *(uint32_t*)(ohB + ni * 8) = pack2h(d[mi][ni][2] + bvB * s, d[mi][ni][3] + bvB * s);
            }
        }
    }
}

// ---------------------------------------------------------------------------
// Tensor-core flash attention (R12-exact): no-max softmax, single fp16,
// 64-row Q tile, double-buffered [K,V], 3 CTA/SM.
// ---------------------------------------------------------------------------
#define P72 72
#define TILB (64 * P72 * 2)      // 9216
#define OQ 0
#define OKV (TILB)               // buffer b at OKV + b*2*TILB: [K, V]
#define OF32 (5 * TILB)          // 46080
#define ATTN_SMEM (OF32 + 3 * 576 * 4)   // 52992

__global__ __launch_bounds__(128, 3) void attn_tc(
    const float* __restrict__ erk, const float* __restrict__ erv)
{
    extern __shared__ __align__(128) char sm[];
    const uint32_t sb = smem_u32(sm);
    float* rqs  = (float*)(sm + OF32);
    float* arel = rqs + 576;
    float* ervs = arel + 576;

    const int bh = blockIdx.y, b = bh >> 3, h = bh & 7;
    const int i0 = blockIdx.x * 64;
    const size_t gb = ((size_t)b * NC + h * DH) * NL;
    const __half* gq = g_q + gb;
    const __half* gkv[2] = {g_k + gb, g_v + gb};

    const int t = threadIdx.x, lane = t & 31, w = t >> 5;
    const int lr = lane >> 2, lc = 2 * (lane & 3);

    const int qrow = (lane & 7) + ((lane >> 4) & 1) * 8, qcol = ((lane >> 3) & 1) * 8;
    const int krow = (lane & 7) + ((lane >> 3) & 1) * 8, kcol = ((lane >> 4) & 1) * 8;
    const int vrow = (lane & 7) + ((lane >> 4) & 1) * 8, vcol = ((lane >> 3) & 1) * 8;

    // Q tile: 512 x 16B chunks
#pragma unroll
    for (int it = 0; it < 4; it++) {
        int e = t + it * 128;
        int row = e >> 3, c16 = e & 7;
        cp16(sb + OQ + row * (P72 * 2) + c16 * 16,
             gq + (size_t)row * NL + i0 + c16 * 8);
    }
    cp_commit();

    auto issue_kv = [&](int buf, int j0g) {
#pragma unroll
        for (int it = 0; it < 8; it++) {
            int e = t + it * 128;
            int mat = e >> 9, rem = e & 511, row = rem >> 3, c16 = rem & 7;
            cp16(sb + OKV + buf * 2 * TILB + mat * TILB + row * (P72 * 2) + c16 * 16,
                 gkv[mat] + (size_t)row * NL + j0g + c16 * 8);
        }
        cp_commit();
    };
    issue_kv(0, 0);

    for (int e = t; e < NT * DH; e += 128) ervs[e] = erv[e];

    cp_wait1();
    __syncthreads();

    {
        const __half* qs = (const __half*)(sm + OQ);
        for (int e = t; e < 64 * NT; e += 128) {
            int r = e / NT, tt = e % NT;
            float s = 0.f;
#pragma unroll 16
            for (int d = 0; d < DH; d++)
                s = fmaf(__half2float(qs[d * P72 + r]), erk[tt * DH + d], s);
            rqs[e] = s;
            arel[e] = 0.f;
        }
    }

    uint32_t qf[4][4];
#pragma unroll
    for (int kc = 0; kc < 4; kc++) {
        uint32_t r = ((kc * 16 + qrow) * P72 + 16 * w + qcol) * 2;
        ld4t(qf[kc], sb + OQ + r);
    }
    __syncthreads();

    float l0 = 0.f, l1 = 0.f;
    float o[8][4];
#pragma unroll
    for (int sbk = 0; sbk < 8; sbk++)
#pragma unroll
        for (int q = 0; q < 4; q++) o[sbk][q] = 0.f;

    const int iloc0 = 16 * w + lr, iloc1 = iloc0 + 8;

    for (int jt = 0; jt < 16; jt++) {
        const int j0 = jt * 64;
        const int buf = jt & 1;
        const bool band = (j0 - i0 <= 64) && (i0 - j0 <= 64);

        __syncthreads();
        if (jt + 1 < 16) { issue_kv(buf ^ 1, j0 + 64); cp_wait1(); }
        else cp_wait0();
        __syncthreads();

        // ---- S = Q K^T ----
        float s[8][4];
#pragma unroll
        for (int sbk = 0; sbk < 8; sbk++)
#pragma unroll
            for (int q = 0; q < 4; q++) s[sbk][q] = 0.f;

        const uint32_t k_b = sb + OKV + buf * 2 * TILB;
#pragma unroll
        for (int nb = 0; nb < 4; nb++) {
#pragma unroll
            for (int kc = 0; kc < 4; kc++) {
                uint32_t r = ((kc * 16 + krow) * P72 + nb * 16 + kcol) * 2;
                uint32_t k4[4];
                ld4t(k4, k_b + r);
                mma_f16(s[2 * nb],     qf[kc], k4);
                mma_f16(s[2 * nb + 1], qf[kc], k4 + 2);
            }
        }

        // ---- rel_k band add ----
        if (band) {
#pragma unroll
            for (int sbk = 0; sbk < 8; sbk++) {
                int jg = j0 + sbk * 8 + lc;
                int t00 = jg - (i0 + iloc0) + WIN;
                int t10 = jg - (i0 + iloc1) + WIN;
                if (t00 >= 0 && t00 < NT)     s[sbk][0] += rqs[iloc0 * NT + t00];
                if (t00 + 1 >= 0 && t00 + 1 < NT) s[sbk][1] += rqs[iloc0 * NT + t00 + 1];
                if (t10 >= 0 && t10 < NT)     s[sbk][2] += rqs[iloc1 * NT + t10];
                if (t10 + 1 >= 0 && t10 + 1 < NT) s[sbk][3] += rqs[iloc1 * NT + t10 + 1];
            }
        }

        // ---- exp + accumulate (no max subtraction; headroom proven) ----
#pragma unroll
        for (int sbk = 0; sbk < 8; sbk++) {
            s[sbk][0] = __expf(s[sbk][0]); l0 += s[sbk][0];
            s[sbk][1] = __expf(s[sbk][1]); l0 += s[sbk][1];
            s[sbk][2] = __expf(s[sbk][2]); l1 += s[sbk][2];
            s[sbk][3] = __expf(s[sbk][3]); l1 += s[sbk][3];
        }

        // ---- band probability accumulator ----
        if (band) {
#pragma unroll
            for (int sbk = 0; sbk < 8; sbk++) {
                int jg = j0 + sbk * 8 + lc;
                int t00 = jg - (i0 + iloc0) + WIN;
                int t10 = jg - (i0 + iloc1) + WIN;
                if (t00 >= 0 && t00 < NT)     arel[iloc0 * NT + t00]     += s[sbk][0];
                if (t00 + 1 >= 0 && t00 + 1 < NT) arel[iloc0 * NT + t00 + 1] += s[sbk][1];
                if (t10 >= 0 && t10 < NT)     arel[iloc1 * NT + t10]     += s[sbk][2];
                if (t10 + 1 >= 0 && t10 + 1 < NT) arel[iloc1 * NT + t10 + 1] += s[sbk][3];
            }
        }

        // ---- pack P ----
        uint32_t pa[4][4];
#pragma unroll
        for (int kc = 0; kc < 4; kc++) {
            pa[kc][0] = pack2h(s[2 * kc][0],     s[2 * kc][1]);
            pa[kc][1] = pack2h(s[2 * kc][2],     s[2 * kc][3]);
            pa[kc][2] = pack2h(s[2 * kc + 1][0], s[2 * kc + 1][1]);
            pa[kc][3] = pack2h(s[2 * kc + 1][2], s[2 * kc + 1][3]);
        }

        // ---- O += P V ----
        const uint32_t v_b = k_b + TILB;
#pragma unroll
        for (int nb = 0; nb < 4; nb++) {
#pragma unroll
            for (int kc = 0; kc < 4; kc++) {
                uint32_t r = ((nb * 16 + vrow) * P72 + kc * 16 + vcol) * 2;
                uint32_t v4[4];
                ld4(v4, v_b + r);
                mma_f16(o[2 * nb],     pa[kc], v4);
                mma_f16(o[2 * nb + 1], pa[kc], v4 + 2);
            }
        }
    }

    // ---- final row-sum reduce ----
    l0 += __shfl_xor_sync(0xffffffffu, l0, 1);
    l0 += __shfl_xor_sync(0xffffffffu, l0, 2);
    l1 += __shfl_xor_sync(0xffffffffu, l1, 1);
    l1 += __shfl_xor_sync(0xffffffffu, l1, 2);
    __syncwarp();

    float inv0 = 1.f / l0, inv1 = 1.f / l1;
    float ar0[NT], ar1[NT];
#pragma unroll
    for (int tt = 0; tt < NT; tt++) {
        ar0[tt] = arel[iloc0 * NT + tt];
        ar1[tt] = arel[iloc1 * NT + tt];
    }
    __half* t0 = g_tT + ((size_t)b * NL + i0 + iloc0) * NC + h * DH;
    __half* t1 = t0 + (size_t)8 * NC;
#pragma unroll
    for (int sbk = 0; sbk < 8; sbk++) {
        int d0 = sbk * 8 + lc;
        float r00 = 0.f, r01 = 0.f, r10 = 0.f, r11 = 0.f;
#pragma unroll
        for (int tt = 0; tt < NT; tt++) {
            float e0 = ervs[tt * DH + d0], e1 = ervs[tt * DH + d0 + 1];
            r00 = fmaf(ar0[tt], e0, r00); r01 = fmaf(ar0[tt], e1, r01);
            r10 = fmaf(ar1[tt], e0, r10); r11 = fmaf(ar1[tt], e1, r11);
        }
        *(uint32_t*)(t0 + d0) = pack2h((o[sbk][0] + r00) * inv0, (o[sbk][1] + r01) * inv0);
        *(uint32_t*)(t1 + d0) = pack2h((o[sbk][2] + r10) * inv1, (o[sbk][3] + r11) * inv1);
    }
}

// ---------------------------------------------------------------------------
extern "C" void kernel_launch(void* const* d_in, const int* in_sizes, int n_in,
                              void* d_out, int out_size)
{
    const float* x   = (const float*)d_in[0];
    const float* Wq  = (const float*)d_in[1];
    const float* bq  = (const float*)d_in[2];
    const float* Wk  = (const float*)d_in[3];
    const float* bk  = (const float*)d_in[4];
    const float* Wv  = (const float*)d_in[5];
    const float* bv  = (const float*)d_in[6];
    const float* Wo  = (const float*)d_in[7];
    const float* bo  = (const float*)d_in[8];
    const float* erk = (const float*)d_in[9];
    const float* erv = (const float*)d_in[10];
    float* out = (float*)d_out;

    __half *xT, *tT, *wh;
    cudaGetSymbolAddress((void**)&xT, g_xT);
    cudaGetSymbolAddress((void**)&tT, g_tT);
    cudaGetSymbolAddress((void**)&wh, g_Wh);

    const int gemm_smem = 2 * BUF2;   // 40960
    cudaFuncSetAttribute(gemm_mma<true>,
                         cudaFuncAttributeMaxDynamicSharedMemorySize, gemm_smem);
    cudaFuncSetAttribute(gemm_mma<false>,
                         cudaFuncAttributeMaxDynamicSharedMemorySize, gemm_smem);
    cudaFuncSetAttribute(attn_tc,
                         cudaFuncAttributeMaxDynamicSharedMemorySize, ATTN_SMEM);

    split_w<<<dim3(NC * NC / 256, 4), 256>>>(Wq, Wk, Wv, Wo);
    split_xT<<<dim3(NL / 32, NC / 32, NB), 256>>>(x);

    const int WSZ = NC * NC;
    gemm_mma<true><<<dim3(NL / 128, 12, NB), 256, gemm_smem>>>(
        wh, xT, bq, bk, bv, nullptr);

    dim3 ga(NL / 64, NB * NH);
    attn_tc<<<ga, 128, ATTN_SMEM>>>(erk, erv);

    gemm_mma<false><<<dim3(NL / 128, 4, NB), 256, gemm_smem>>>(
        wh + 3 * WSZ, tT, bo, nullptr, nullptr, out);
}